// round 13
// baseline (speedup 1.0000x reference)
#include <cuda_runtime.h>
#include <cuda_bf16.h>

// Cascaded 16-tap FIR pair == single 33-tap causal conv for columns i >= 32:
//   y[i] = x[i] + sum_{j=1}^{32} g[j] * x[i-j],  g = [1,h] (*) [1,h_rev]
// Columns [0,32) computed exactly (v-mask aware) by lanes 0-3 on row-start tiles.
//
// ROW-PAIRED fma.rn.f32x2: rows (2p, 2p+1) processed together; smem tile holds
// the two rows element-interleaved, so EVERY multiplicand pair (x0[c], x1[c])
// is an aligned float2 -> zero register-pair marshalling (the failure mode of
// the two earlier f32x2 attempts). Tap pairs (g,g) pre-broadcast in smem.
// Accumulator pair = (y0[i], y1[i]), unpacked only at the store.
// Barrier-free warp streams (R12) + cp.async double-buffered scratch +
// per-tile smem interleave pass ordered by __syncwarp.
//
// B=256 rows, N=131072 cols, F=16.

#define F       16
#define GT      33
#define THREADS 256
#define WARPS   8
#define WCOLS   256                // output columns per warp-tile (x 2 rows)
#define HALO    32
#define SPAN    (WCOLS + HALO)     // 288 staged columns
#define NCOL    131072
#define NROW    256
#define TPR     (NCOL / WCOLS)     // 512 tiles per row-pair
#define NWT     (TPR * (NROW / 2)) // 65536 warp-tiles
#define NBLK    296                // 2 CTAs per SM
#define NSTREAM (NBLK * WARPS)     // 2368 warp streams

// per-warp smem slot (floats):
//   scr0 @0 (576 = 2 rows x 288), scr1 @576, inter @1152 (36 seg x 20),
//   sgq @1872 (32 float2 tap pairs)
#define SCRSZ   576
#define INT_OFF 1152
#define SGQ_OFF 1872
#define WSLOT   1936
#define SMEM_DYN (WARPS * WSLOT * 4)       // 61952 B

typedef unsigned long long u64;

#define FMA2(d, a, b, c) \
    asm("fma.rn.f32x2 %0, %1, %2, %3;" : "=l"(d) : "l"(a), "l"(b), "l"(c))
#define UNPACK2(lo, hi, p) \
    asm("mov.b64 {%0, %1}, %2;" : "=f"(lo), "=f"(hi) : "l"(p))

__device__ __forceinline__ void cp16(unsigned dst, const float4* src, int sz) {
    asm volatile("cp.async.cg.shared.global [%0], [%1], 16, %2;"
                 :: "r"(dst), "l"(src), "r"(sz));
}
__device__ __forceinline__ void cp_commit() {
    asm volatile("cp.async.commit_group;");
}
template <int N> __device__ __forceinline__ void cp_wait() {
    asm volatile("cp.async.wait_group %0;" :: "n"(N));
}

// Stage both rows of warp-tile wt into scratch (row-major, row1 at +288).
__device__ __forceinline__ void stage_wt(unsigned sb, const float* x,
                                         int wt, int lane)
{
    const int p   = wt / TPR;
    const int tir = wt % TPR;
    const float4* s0 = reinterpret_cast<const float4*>(
        x + (size_t)(2 * p) * NCOL + tir * WCOLS - HALO);
    const float4* s1 = reinterpret_cast<const float4*>(
        x + (size_t)(2 * p + 1) * NCOL + tir * WCOLS - HALO);
    const bool z = (tir == 0);
#pragma unroll
    for (int vk = lane; vk < SPAN / 4; vk += 32) {
        const int sz = (z && vk < HALO / 4) ? 0 : 16;
        const float4* a = sz ? (s0 + vk) : reinterpret_cast<const float4*>(x);
        const float4* b = sz ? (s1 + vk) : reinterpret_cast<const float4*>(x);
        cp16(sb + vk * 16, a, sz);
        cp16(sb + SCRSZ / 2 * 4 + vk * 16, b, sz);
    }
}

__global__ __launch_bounds__(THREADS, 2)
void fir2_fused(const float* __restrict__ x,
                const float* __restrict__ h,
                float* __restrict__ y)
{
    extern __shared__ float smem[];

    const int tid  = threadIdx.x;
    const int wid  = tid >> 5;
    const int lane = tid & 31;

    float* const wbase = smem + wid * WSLOT;
    float* const inter = wbase + INT_OFF;
    float* const sgqf  = wbase + SGQ_OFF;
    const unsigned sbw = (unsigned)__cvta_generic_to_shared(wbase);

    // ---- combined taps, computed per thread; pair-broadcast into sgq -------
    {
        float hh[F];
#pragma unroll
        for (int j = 0; j < F; j++) hh[j] = __ldg(h + j);
        if (lane < 32) {
            const int j = lane + 1;            // tap index 1..32
            float acc = 0.0f;
            const int a0 = (j > F) ? (j - F) : 0;
            const int a1 = (j < F) ? j : F;
#pragma unroll
            for (int a = 0; a <= F; a++) {
                if (a >= a0 && a <= a1) {
                    const float ka = (a == 0) ? 1.0f : hh[a - 1];
                    const int bb = j - a;
                    const float kb = (bb == 0) ? 1.0f : hh[F - bb];
                    acc += ka * kb;
                }
            }
            *reinterpret_cast<float2*>(sgqf + 2 * lane) = make_float2(acc, acc);
        }
    }
    __syncwarp();

    // ---- warp-stream persistent loop ---------------------------------------
    int wt = blockIdx.x * WARPS + wid;
    if (wt < NWT) stage_wt(sbw, x, wt, lane);
    cp_commit();

    int buf = 0;
    for (; wt < NWT; wt += NSTREAM, buf ^= 1) {
        const int wtn = wt + NSTREAM;
        if (wtn < NWT) stage_wt(sbw + (buf ^ 1) * (SCRSZ * 4), x, wtn, lane);
        cp_commit();
        cp_wait<1>();                       // current scratch landed
        __syncwarp();                       // prev window reads done (RAW/WAR)

        // ---- interleave scratch[buf] -> inter (padded 8-col segments) ------
        {
            const float* s0 = wbase + buf * SCRSZ;
#pragma unroll
            for (int vk = lane; vk < SPAN / 4; vk += 32) {
                const float4 a = *reinterpret_cast<const float4*>(s0 + 4 * vk);
                const float4 b = *reinterpret_cast<const float4*>(s0 + SCRSZ / 2 + 4 * vk);
                const int cc = 4 * vk;
                float* ib = inter + 20 * (cc >> 3) + (cc & 7) * 2;
                *reinterpret_cast<float2*>(ib + 0) = make_float2(a.x, b.x);
                *reinterpret_cast<float2*>(ib + 2) = make_float2(a.y, b.y);
                *reinterpret_cast<float2*>(ib + 4) = make_float2(a.z, b.z);
                *reinterpret_cast<float2*>(ib + 6) = make_float2(a.w, b.w);
            }
        }
        __syncwarp();                       // interleave visible to all lanes

        const int p   = wt / TPR;
        const int tir = wt % TPR;
        const int t0  = tir * WCOLS;
        const size_t r0off = (size_t)(2 * p) * NCOL;

        if (!(tir == 0 && lane < 4)) {
            u64 acc[8];

#pragma unroll
            for (int c = 0; c < 4; c++) {
                // tap pairs for this chunk: j = 8c+1 .. 8c+8
                u64 tp[8];
                {
                    const float* tb = sgqf + 16 * c;
#pragma unroll
                    for (int q = 0; q < 4; q++) {
                        const ulonglong2 v =
                            *reinterpret_cast<const ulonglong2*>(tb + 4 * q);
                        tp[2 * q]     = v.x;
                        tp[2 * q + 1] = v.y;
                    }
                }
                // 16-col interleaved slice: segments (3+lane-c), (4+lane-c)
                u64 wd[16];
                {
                    const int s = 3 + lane - c;
                    const float* ip = inter + 20 * s;
#pragma unroll
                    for (int q = 0; q < 4; q++) {
                        const ulonglong2 v =
                            *reinterpret_cast<const ulonglong2*>(ip + 4 * q);
                        wd[2 * q]     = v.x;
                        wd[2 * q + 1] = v.y;
                    }
                    const float* ip2 = inter + 20 * (s + 1);
#pragma unroll
                    for (int q = 0; q < 4; q++) {
                        const ulonglong2 v =
                            *reinterpret_cast<const ulonglong2*>(ip2 + 4 * q);
                        wd[8 + 2 * q]     = v.x;
                        wd[8 + 2 * q + 1] = v.y;
                    }
                }
                if (c == 0) {
                    // identity tap: acc[r] = (x0[i], x1[i]) = wd[8+r]
#pragma unroll
                    for (int r = 0; r < 8; r++) acc[r] = wd[8 + r];
                }
                // taps j = 8c+k (k=1..8): operand col index m = r - k + 8
#pragma unroll
                for (int k = 1; k <= 8; k++) {
#pragma unroll
                    for (int r = 0; r < 8; r++)
                        FMA2(acc[r], tp[k - 1], wd[r - k + 8], acc[r]);
                }
            }

            // ---- deinterleave + store both rows ----------------------------
            float o0[8], o1[8];
#pragma unroll
            for (int r = 0; r < 8; r++) UNPACK2(o0[r], o1[r], acc[r]);

            float4* y0 = reinterpret_cast<float4*>(y + r0off + t0 + 8 * lane);
            float4* y1 = reinterpret_cast<float4*>(y + r0off + NCOL + t0 + 8 * lane);
            y0[0] = make_float4(o0[0], o0[1], o0[2], o0[3]);
            y0[1] = make_float4(o0[4], o0[5], o0[6], o0[7]);
            y1[0] = make_float4(o1[0], o1[1], o1[2], o1[3]);
            y1[1] = make_float4(o1[4], o1[5], o1[6], o1[7]);
        } else {
            // ---- exact masked two-stage result, cols [0,32), both rows -----
            // lane 0: row0 zeros; lane 1: row0 compute;
            // lane 2: row1 zeros; lane 3: row1 compute.
            const size_t ro = r0off + (size_t)(lane >> 1) * NCOL;
            if ((lane & 1) == 0) {
                float4* yo = reinterpret_cast<float4*>(y + ro);
#pragma unroll
                for (int q = 0; q < 4; q++)
                    yo[q] = make_float4(0.f, 0.f, 0.f, 0.f);   // y[0..16) = 0
            } else {
                const float* xr = x + ro;
                float xa[32];
#pragma unroll
                for (int cc = 0; cc < 32; cc++) xa[cc] = xr[cc];
                float hh[F];
#pragma unroll
                for (int j = 0; j < F; j++) hh[j] = __ldg(h + j);

                float va[F];               // v[16..31]
#pragma unroll
                for (int tt = 0; tt < F; tt++) {
                    const int k = F + tt;
                    float a2 = xa[k];
#pragma unroll
                    for (int j = 0; j < F; j++)
                        a2 = fmaf(hh[j], xa[k - 1 - j], a2);
                    va[tt] = a2;
                }
                float ya[F];               // y[16..31]
#pragma unroll
                for (int tt = 0; tt < F; tt++) {
                    const int i = F + tt;
                    float a2 = va[tt];
#pragma unroll
                    for (int m = 0; m < F; m++) {
                        const int k = i - F + m;   // v index; masked if < 16
                        if (k >= F) a2 = fmaf(hh[m], va[k - F], a2);
                    }
                    ya[tt] = a2;
                }
                float4* yo = reinterpret_cast<float4*>(y + ro + F);
#pragma unroll
                for (int q = 0; q < 4; q++)
                    yo[q] = make_float4(ya[4 * q], ya[4 * q + 1],
                                        ya[4 * q + 2], ya[4 * q + 3]);
            }
        }
        // No block barriers anywhere; per-warp ordering via the two
        // __syncwarp()s above + in-order issue.
    }
}

extern "C" void kernel_launch(void* const* d_in, const int* in_sizes, int n_in,
                              void* d_out, int out_size)
{
    const float* x = (const float*)d_in[0];   // (256, 131072) f32
    const float* h = (const float*)d_in[1];   // (1, 16) f32
    float* y = (float*)d_out;                 // (256, 131072) f32

    cudaFuncSetAttribute(fir2_fused,
                         cudaFuncAttributeMaxDynamicSharedMemorySize, SMEM_DYN);
    fir2_fused<<<NBLK, THREADS, SMEM_DYN>>>(x, h, y);
}

// round 14
// speedup vs baseline: 1.0681x; 1.0681x over previous
#include <cuda_runtime.h>
#include <cuda_bf16.h>

// Cascaded 16-tap FIR pair == single 33-tap causal conv for columns i >= 32:
//   y[i] = x[i] + sum_{j=1}^{32} g[j] * x[i-j],  g = [1,h] (*) [1,h_rev]
// Columns [0,32) computed exactly (v-mask aware) by lanes 0-3 on row-start tiles.
//
// ROW-PAIRED fma.rn.f32x2, v2: interleaving done DURING staging via 4-byte
// cp.async (x0[c] -> inter[2c], x1[c] -> inter[2c+1]) -> no smem interleave
// pass. Tap pairs and the full 40-pair window live in registers; the inner
// loop is one flat burst of 256 FFMA2 with no memory ops. Barrier-free warp
// streams, per-warp double-buffered interleaved tile.
//
// B=256 rows, N=131072 cols, F=16.

#define F       16
#define GT      33
#define THREADS 256
#define WARPS   8
#define WCOLS   256                // output columns per warp-tile (x 2 rows)
#define HALO    32
#define SPAN    (WCOLS + HALO)     // 288 staged columns
#define NCOL    131072
#define NROW    256
#define TPR     (NCOL / WCOLS)     // 512 tiles per row-pair
#define NWT     (TPR * (NROW / 2)) // 65536 warp-tiles
#define NBLK    296                // 2 CTAs per SM
#define NSTREAM (NBLK * WARPS)     // 2368 warp streams

// interleaved tile: 36 segments of 8 col-pairs, padded 16->20 floats/segment
#define SEGP    20
#define NSEG    (SPAN / 8)                 // 36
#define BUFW    (NSEG * SEGP)              // 720 floats per buffer
#define WSLOT   (2 * BUFW)                 // double-buffered, per warp
#define SMEM_DYN (WARPS * WSLOT * 4)       // 46080 B

typedef unsigned long long u64;

#define FMA2(d, a, b, c) \
    asm("fma.rn.f32x2 %0, %1, %2, %3;" : "=l"(d) : "l"(a), "l"(b), "l"(c))
#define PACK2(p, lo, hi) \
    asm("mov.b64 %0, {%1, %2};" : "=l"(p) : "f"(lo), "f"(hi))
#define UNPACK2(lo, hi, p) \
    asm("mov.b64 {%0, %1}, %2;" : "=f"(lo), "=f"(hi) : "l"(p))

__device__ __forceinline__ void cp4(unsigned dst, const float* src, int sz) {
    asm volatile("cp.async.ca.shared.global [%0], [%1], 4, %2;"
                 :: "r"(dst), "l"(src), "r"(sz));
}
__device__ __forceinline__ void cp_commit() {
    asm volatile("cp.async.commit_group;");
}
template <int N> __device__ __forceinline__ void cp_wait() {
    asm volatile("cp.async.wait_group %0;" :: "n"(N));
}

// Stage warp-tile wt interleaved: staged col sc in [0, 288) holds
// (x0[t0-32+sc], x1[t0-32+sc]) at inter float index 20*(sc>>3)+2*(sc&7)+row.
__device__ __forceinline__ void stage_wt(unsigned sb, const float* x,
                                         int wt, int lane)
{
    const int p   = wt / TPR;
    const int tir = wt % TPR;
    const float* s0 = x + (size_t)(2 * p) * NCOL + tir * WCOLS - HALO;
    const float* s1 = s0 + NCOL;
    const bool z = (tir == 0);
#pragma unroll
    for (int k = 0; k < SPAN / 32; k++) {          // 9 iters
        const int sc = lane + 32 * k;
        const int sz = (z && sc < HALO) ? 0 : 4;
        const float* a = sz ? (s0 + sc) : x;
        const float* b = sz ? (s1 + sc) : x;
        const unsigned d = sb + ((20 * (sc >> 3) + 2 * (sc & 7)) << 2);
        cp4(d, a, sz);
        cp4(d + 4, b, sz);
    }
}

__global__ __launch_bounds__(THREADS, 2)
void fir2_fused(const float* __restrict__ x,
                const float* __restrict__ h,
                float* __restrict__ y)
{
    extern __shared__ float smem[];

    const int tid  = threadIdx.x;
    const int wid  = tid >> 5;
    const int lane = tid & 31;

    float* const wbase = smem + wid * WSLOT;
    const unsigned sbw = (unsigned)__cvta_generic_to_shared(wbase);

    // ---- combined taps: per-thread, packed (g,g) into registers ------------
    float hh[F];
#pragma unroll
    for (int j = 0; j < F; j++) hh[j] = __ldg(h + j);

    u64 tp[32];                                // tp[j-1] = (g[j], g[j])
#pragma unroll
    for (int j = 1; j < GT; j++) {
        float acc = 0.0f;
        const int a0 = (j > F) ? (j - F) : 0;
        const int a1 = (j < F) ? j : F;
#pragma unroll
        for (int a = 0; a <= F; a++) {
            if (a >= a0 && a <= a1) {
                const float ka = (a == 0) ? 1.0f : hh[a - 1];
                const int bb = j - a;
                const float kb = (bb == 0) ? 1.0f : hh[F - bb];
                acc += ka * kb;
            }
        }
        PACK2(tp[j - 1], acc, acc);
    }

    // ---- warp-stream persistent loop ---------------------------------------
    int wt = blockIdx.x * WARPS + wid;
    if (wt < NWT) stage_wt(sbw, x, wt, lane);
    cp_commit();

    int buf = 0;
    for (; wt < NWT; wt += NSTREAM, buf ^= 1) {
        const int wtn = wt + NSTREAM;
        if (wtn < NWT) stage_wt(sbw + (buf ^ 1) * (BUFW * 4), x, wtn, lane);
        cp_commit();
        cp_wait<1>();                       // current buffer's group landed
        __syncwarp();

        const int p   = wt / TPR;
        const int tir = wt % TPR;
        const int t0  = tir * WCOLS;
        const size_t r0off = (size_t)(2 * p) * NCOL;
        const float* sxc = wbase + buf * BUFW;

        if (!(tir == 0 && lane < 4)) {
            // ---- window: wd[k] = pair at staged col (8*lane + k), k in [0,40)
            // lane's outputs: col-pairs t0 + 8*lane + r, r in [0,8)
            u64 wd[40];
            {
#pragma unroll
                for (int s = 0; s < 5; s++) {
                    const float* ip = sxc + 20 * (lane + s);
#pragma unroll
                    for (int q = 0; q < 4; q++) {
                        const ulonglong2 v =
                            *reinterpret_cast<const ulonglong2*>(ip + 4 * q);
                        wd[8 * s + 2 * q]     = v.x;
                        wd[8 * s + 2 * q + 1] = v.y;
                    }
                }
            }

            u64 acc[8];
#pragma unroll
            for (int r = 0; r < 8; r++) acc[r] = wd[32 + r];   // identity tap

#pragma unroll
            for (int j = 1; j < GT; j++) {
#pragma unroll
                for (int r = 0; r < 8; r++)
                    FMA2(acc[r], tp[j - 1], wd[32 + r - j], acc[r]);
            }

            // ---- deinterleave + store both rows ----------------------------
            float o0[8], o1[8];
#pragma unroll
            for (int r = 0; r < 8; r++) UNPACK2(o0[r], o1[r], acc[r]);

            float4* y0 = reinterpret_cast<float4*>(y + r0off + t0 + 8 * lane);
            float4* y1 = reinterpret_cast<float4*>(y + r0off + NCOL + t0 + 8 * lane);
            y0[0] = make_float4(o0[0], o0[1], o0[2], o0[3]);
            y0[1] = make_float4(o0[4], o0[5], o0[6], o0[7]);
            y1[0] = make_float4(o1[0], o1[1], o1[2], o1[3]);
            y1[1] = make_float4(o1[4], o1[5], o1[6], o1[7]);
        } else {
            // ---- exact masked two-stage result, cols [0,32), both rows -----
            // lane 0: row0 zeros; lane 1: row0 compute;
            // lane 2: row1 zeros; lane 3: row1 compute.
            const size_t ro = r0off + (size_t)(lane >> 1) * NCOL;
            if ((lane & 1) == 0) {
                float4* yo = reinterpret_cast<float4*>(y + ro);
#pragma unroll
                for (int q = 0; q < 4; q++)
                    yo[q] = make_float4(0.f, 0.f, 0.f, 0.f);   // y[0..16) = 0
            } else {
                const float* xr = x + ro;
                float xa[32];
#pragma unroll
                for (int cc = 0; cc < 32; cc++) xa[cc] = xr[cc];

                float va[F];               // v[16..31]
#pragma unroll
                for (int tt = 0; tt < F; tt++) {
                    const int k = F + tt;
                    float a2 = xa[k];
#pragma unroll
                    for (int j = 0; j < F; j++)
                        a2 = fmaf(hh[j], xa[k - 1 - j], a2);
                    va[tt] = a2;
                }
                float ya[F];               // y[16..31]
#pragma unroll
                for (int tt = 0; tt < F; tt++) {
                    const int i = F + tt;
                    float a2 = va[tt];
#pragma unroll
                    for (int m = 0; m < F; m++) {
                        const int k = i - F + m;   // v index; masked if < 16
                        if (k >= F) a2 = fmaf(hh[m], va[k - F], a2);
                    }
                    ya[tt] = a2;
                }
                float4* yo = reinterpret_cast<float4*>(y + ro + F);
#pragma unroll
                for (int q = 0; q < 4; q++)
                    yo[q] = make_float4(ya[4 * q], ya[4 * q + 1],
                                        ya[4 * q + 2], ya[4 * q + 3]);
            }
        }
        // No block barriers. Per-warp ordering: in-order issue + __syncwarp;
        // WAR on buffers is safe because each buffer's LDS reads feed FFMA2s
        // that issue before the next cp.async write to that buffer issues.
    }
}

extern "C" void kernel_launch(void* const* d_in, const int* in_sizes, int n_in,
                              void* d_out, int out_size)
{
    const float* x = (const float*)d_in[0];   // (256, 131072) f32
    const float* h = (const float*)d_in[1];   // (1, 16) f32
    float* y = (float*)d_out;                 // (256, 131072) f32

    cudaFuncSetAttribute(fir2_fused,
                         cudaFuncAttributeMaxDynamicSharedMemorySize, SMEM_DYN);
    fir2_fused<<<NBLK, THREADS, SMEM_DYN>>>(x, h, y);
}